// round 10
// baseline (speedup 1.0000x reference)
#include <cuda_runtime.h>
#include <cuda_fp16.h>
#include <cuda_bf16.h>

#define NMAX 100000
#define EMAX 1600000
#define SCAN_CHUNK 1024

// ---------------------------------------------------------------------------
// Scratch (device globals — zero-init at load; each consumer restores zeros
// so the invariant holds across CUDA-graph replays).
// ---------------------------------------------------------------------------
__device__ int    g_deg[NMAX];
__device__ int    g_off[NMAX];        // CSR range begin (by dst)
__device__ int    g_end[NMAX];        // CSR range end
__device__ int    g_rank[EMAX];       // edge rank within its dst bucket
__device__ int    g_csrc[EMAX];       // CSR column = src node BYTE offset (s*64)
__device__ int    g_base;             // global edge-slot counter
__device__ float  g_dinv[NMAX];
__device__ float  g_xs[NMAX * 4];     // x * dinv (pre-scaled layer-1 sources)
__device__ float  g_a1[NMAX * 4];     // layer-1 aggregate (REDs from k_fill)
__device__ __half g_h2h[NMAX * 32];   // (relu(v@W1+b1) @ W2) * dinv, fp16

// ---------------------------------------------------------------------------
// PTX helpers
// ---------------------------------------------------------------------------
__device__ __forceinline__ void red_add_v4(float* p, float4 v) {
    asm volatile(
        "{\n\t"
        ".reg .u64 q;\n\t"
        "cvta.to.global.u64 q, %0;\n\t"
        "red.global.add.v4.f32 [q], {%1, %2, %3, %4};\n\t"
        "}"
        :: "l"(p), "f"(v.x), "f"(v.y), "f"(v.z), "f"(v.w)
        : "memory");
}

// packed fp32x2 FMA (Blackwell FFMA2): d = a*b + d
__device__ __forceinline__ void ffma2(unsigned long long& d,
                                      unsigned long long a,
                                      unsigned long long b) {
    asm("fma.rn.f32x2 %0, %1, %2, %0;" : "+l"(d) : "l"(a), "l"(b));
}

__device__ __forceinline__ unsigned long long pack2(float lo, float hi) {
    unsigned long long r;
    asm("mov.b64 %0, {%1, %2};" : "=l"(r) : "f"(lo), "f"(hi));
    return r;
}

__device__ __forceinline__ void unpack2(float& lo, float& hi,
                                        unsigned long long v) {
    asm("mov.b64 {%0, %1}, %2;" : "=f"(lo), "=f"(hi) : "l"(v));
}

// ---------------------------------------------------------------------------
// K1: degree over dst; rank[e] = arrival index within bucket; resets g_base
// ---------------------------------------------------------------------------
__global__ void k_deg(const int* __restrict__ dst, int E) {
    int e = blockIdx.x * blockDim.x + threadIdx.x;
    if (e == 0) g_base = 0;
    if (e < E) g_rank[e] = atomicAdd(&g_deg[dst[e]], 1);
}

// ---------------------------------------------------------------------------
// K2: single-pass chunked scan, atomic base per 1024-chunk (bucket ranges
//     disjoint, not globally sorted — g_end stores explicit ends). Also
//     computes dinv, pre-scales x, and ZEROES g_deg.
// ---------------------------------------------------------------------------
__global__ void __launch_bounds__(SCAN_CHUNK) k_scan(const float4* __restrict__ x4, int n) {
    __shared__ int swarp[32];
    __shared__ int sbase;
    int t = threadIdx.x;
    int lane = t & 31, wid = t >> 5;
    int i = blockIdx.x * SCAN_CHUNK + t;
    int v = (i < n) ? g_deg[i] : 0;

    int inc = v;
#pragma unroll
    for (int o = 1; o < 32; o <<= 1) {
        int y = __shfl_up_sync(0xffffffff, inc, o);
        if (lane >= o) inc += y;
    }
    if (lane == 31) swarp[wid] = inc;
    __syncthreads();
    if (t < 32) {
        int wv = swarp[t];
        int winc = wv;
#pragma unroll
        for (int o = 1; o < 32; o <<= 1) {
            int y = __shfl_up_sync(0xffffffff, winc, o);
            if (t >= o) winc += y;
        }
        swarp[t] = winc - wv;                          // exclusive warp base
        if (t == 31) sbase = atomicAdd(&g_base, winc); // winc = block total
    }
    __syncthreads();

    if (i < n) {
        int beg = sbase + swarp[wid] + (inc - v);
        g_off[i] = beg;
        g_end[i] = beg + v;
        float di = rsqrtf((float)(v + 1));             // +1 self-loop
        g_dinv[i] = di;
        float4 xv = x4[i];
        xv.x *= di; xv.y *= di; xv.z *= di; xv.w *= di;
        *(float4*)&g_xs[i * 4] = xv;
        g_deg[i] = 0;                                  // restore scratch
    }
}

// ---------------------------------------------------------------------------
// K3: bucket-fill CSR (atomic-free via precomputed rank) + layer-1 scatter:
//     csrc[off[d]+rank[e]] = src[e]*64 (byte offset);  a1[dst] += xs[src]
// ---------------------------------------------------------------------------
__global__ void k_fill(const int* __restrict__ src,
                       const int* __restrict__ dst, int E) {
    int e = blockIdx.x * blockDim.x + threadIdx.x;
    if (e >= E) return;
    int s = src[e], d = dst[e];
    g_csrc[g_off[d] + g_rank[e]] = s << 6;   // byte offset into g_h2h row
    red_add_v4(&g_a1[d * 4], *(const float4*)&g_xs[s * 4]);
}

// ---------------------------------------------------------------------------
// K4: layer-1 transform. 128-thread blocks (7 resident blocks/SM -> high
//     occupancy; R9's 256-thr config quantized to 1 block/SM = 25% occ).
//     Each thread: TWO nodes (A=i, B=i+64) x one 16-output half (q).
//     FFMA2 datapath; W2 loads amortize over both nodes. Zeroes g_a1.
// ---------------------------------------------------------------------------
__global__ void __launch_bounds__(128) k_layer1(
        const float* __restrict__ W1,   // [4,64]
        const float* __restrict__ b1,   // [64]
        const float* __restrict__ W2,   // [64,32]
        int n) {
    __shared__ float4 sW1t[64];                 // column f of W1
    __shared__ float  sb1[64];
    __shared__ unsigned long long sW2p[64 * 16];// row f as 16 f32x2 pairs
    int t = threadIdx.x;
    if (t < 64) {
        sW1t[t] = make_float4(W1[t], W1[64 + t], W1[128 + t], W1[192 + t]);
        sb1[t] = b1[t];
    }
    for (int i = t; i < 1024; i += 128)
        sW2p[i] = ((const unsigned long long*)W2)[i];
    __syncthreads();

    int q = t & 1;                    // output half: features [q*16, q*16+16)
    int iA = blockIdx.x * 128 + (t >> 1);
    int iB = iA + 64;
    if (iA >= n) return;
    bool hasB = (iB < n);

    float diA = g_dinv[iA];
    float4 aA  = *(const float4*)&g_a1[iA * 4];
    float4 xA  = *(const float4*)&g_xs[iA * 4];
    if (q == 0) *(float4*)&g_a1[iA * 4] = make_float4(0.f, 0.f, 0.f, 0.f);
    float vA0 = (aA.x + xA.x) * diA, vA1 = (aA.y + xA.y) * diA;
    float vA2 = (aA.z + xA.z) * diA, vA3 = (aA.w + xA.w) * diA;

    float diB = 0.f, vB0 = 0.f, vB1 = 0.f, vB2 = 0.f, vB3 = 0.f;
    if (hasB) {
        diB = g_dinv[iB];
        float4 aB = *(const float4*)&g_a1[iB * 4];
        float4 xB = *(const float4*)&g_xs[iB * 4];
        if (q == 0) *(float4*)&g_a1[iB * 4] = make_float4(0.f, 0.f, 0.f, 0.f);
        vB0 = (aB.x + xB.x) * diB; vB1 = (aB.y + xB.y) * diB;
        vB2 = (aB.z + xB.z) * diB; vB3 = (aB.w + xB.w) * diB;
    }

    unsigned long long accA[8], accB[8];
#pragma unroll
    for (int c = 0; c < 8; c++) { accA[c] = 0ull; accB[c] = 0ull; }

    const ulonglong2* w2p = (const ulonglong2*)&sW2p[q * 8];

#pragma unroll 8
    for (int f = 0; f < 64; f++) {
        float4 w1 = sW1t[f];
        float bb = sb1[f];
        float hA = fmaf(vA0, w1.x, fmaf(vA1, w1.y,
                   fmaf(vA2, w1.z, fmaf(vA3, w1.w, bb))));
        hA = fmaxf(hA, 0.0f);
        float hB = fmaf(vB0, w1.x, fmaf(vB1, w1.y,
                   fmaf(vB2, w1.z, fmaf(vB3, w1.w, bb))));
        hB = fmaxf(hB, 0.0f);
        unsigned long long hhA = pack2(hA, hA);
        unsigned long long hhB = pack2(hB, hB);

        const ulonglong2* w2 = (const ulonglong2*)((const unsigned long long*)w2p + f * 16);
        ulonglong2 p0 = w2[0], p1 = w2[1], p2 = w2[2], p3 = w2[3];
        ffma2(accA[0], p0.x, hhA); ffma2(accB[0], p0.x, hhB);
        ffma2(accA[1], p0.y, hhA); ffma2(accB[1], p0.y, hhB);
        ffma2(accA[2], p1.x, hhA); ffma2(accB[2], p1.x, hhB);
        ffma2(accA[3], p1.y, hhA); ffma2(accB[3], p1.y, hhB);
        ffma2(accA[4], p2.x, hhA); ffma2(accB[4], p2.x, hhB);
        ffma2(accA[5], p2.y, hhA); ffma2(accB[5], p2.y, hhB);
        ffma2(accA[6], p3.x, hhA); ffma2(accB[6], p3.x, hhB);
        ffma2(accA[7], p3.y, hhA); ffma2(accB[7], p3.y, hhB);
    }

    {
        __half2 hp[4];
#pragma unroll
        for (int c = 0; c < 4; c++) {
            float lo, hi;
            unpack2(lo, hi, accA[c]);
            hp[c] = __floats2half2_rn(lo * diA, hi * diA);
        }
        ((float4*)&g_h2h[iA * 32 + q * 16])[0] = *(const float4*)hp;
#pragma unroll
        for (int c = 0; c < 4; c++) {
            float lo, hi;
            unpack2(lo, hi, accA[c + 4]);
            hp[c] = __floats2half2_rn(lo * diA, hi * diA);
        }
        ((float4*)&g_h2h[iA * 32 + q * 16])[1] = *(const float4*)hp;
    }
    if (hasB) {
        __half2 hp[4];
#pragma unroll
        for (int c = 0; c < 4; c++) {
            float lo, hi;
            unpack2(lo, hi, accB[c]);
            hp[c] = __floats2half2_rn(lo * diB, hi * diB);
        }
        ((float4*)&g_h2h[iB * 32 + q * 16])[0] = *(const float4*)hp;
#pragma unroll
        for (int c = 0; c < 4; c++) {
            float lo, hi;
            unpack2(lo, hi, accB[c + 4]);
            hp[c] = __floats2half2_rn(lo * diB, hi * diB);
        }
        ((float4*)&g_h2h[iB * 32 + q * 16])[1] = *(const float4*)hp;
    }
}

// ---------------------------------------------------------------------------
// K5: fused layer 2 + final linear. TWO nodes per warp:
//     lane = (half = lane>>4, j2 = lane&15) -> feature pair (2*j2, 2*j2+1)
//     Gather: one __half2 per lane per edge; a warp-instruction covers 2 edges.
//     h2  = relu(dinv*(sum_s h2h[s] + h2h[node]) + b2)
//     out = relu(h2 @ Wf + bf)
// ---------------------------------------------------------------------------
__global__ void __launch_bounds__(256) k_final(
        const float* __restrict__ b2,   // [32]
        const float* __restrict__ Wf,   // [32,32]
        const float* __restrict__ bf,   // [32]
        float* __restrict__ out, int n) {
    __shared__ float sWf[32 * 32];
    __shared__ float sb2[32];
    __shared__ float sbf[32];
    __shared__ float sh[16][32];        // 16 nodes per 256-thread block
    int t = threadIdx.x;
    for (int i = t; i < 1024; i += 256) sWf[i] = Wf[i];
    if (t < 32) { sb2[t] = b2[t]; sbf[t] = bf[t]; }
    __syncthreads();

    int w = t >> 5;
    int lane = t & 31;
    int half = lane >> 4;               // which node of the warp's pair
    int j2 = lane & 15;                 // feature pair index
    int slot = w * 2 + half;
    int node = blockIdx.x * 16 + slot;
    bool active = (node < n);

    const char* h2base = (const char*)g_h2h;
    int foff = j2 << 2;                 // byte offset of feature pair

    float ax = 0.0f, ay = 0.0f;
    float di = 0.0f;
    float2 selff = make_float2(0.f, 0.f);
    if (active) {
        int beg = g_off[node], end = g_end[node];
        int i = beg;
        for (; i + 4 <= end; i += 4) {
            int o0 = g_csrc[i + 0], o1 = g_csrc[i + 1];
            int o2 = g_csrc[i + 2], o3 = g_csrc[i + 3];
            __half2 m0 = *(const __half2*)(h2base + o0 + foff);
            __half2 m1 = *(const __half2*)(h2base + o1 + foff);
            __half2 m2 = *(const __half2*)(h2base + o2 + foff);
            __half2 m3 = *(const __half2*)(h2base + o3 + foff);
            float2 f0 = __half22float2(m0), f1 = __half22float2(m1);
            float2 f2 = __half22float2(m2), f3 = __half22float2(m3);
            ax += (f0.x + f1.x) + (f2.x + f3.x);
            ay += (f0.y + f1.y) + (f2.y + f3.y);
        }
        for (; i < end; i++) {
            __half2 m = *(const __half2*)(h2base + g_csrc[i] + foff);
            float2 f = __half22float2(m);
            ax += f.x; ay += f.y;
        }
        di = g_dinv[node];
        selff = __half22float2(*(const __half2*)(h2base + (node << 6) + foff));
    }

    float2 bb2 = *(const float2*)&sb2[j2 * 2];
    float h0 = fmaxf(fmaf(di, ax + selff.x, bb2.x), 0.0f);
    float h1 = fmaxf(fmaf(di, ay + selff.y, bb2.y), 0.0f);
    sh[slot][j2 * 2]     = h0;
    sh[slot][j2 * 2 + 1] = h1;
    __syncwarp();
    if (!active) return;

    float2 bbf = *(const float2*)&sbf[j2 * 2];
    float o0 = bbf.x, o1 = bbf.y;
#pragma unroll
    for (int k = 0; k < 32; k++) {
        float hk = sh[slot][k];
        float2 wv = *(const float2*)&sWf[k * 32 + j2 * 2];
        o0 = fmaf(hk, wv.x, o0);
        o1 = fmaf(hk, wv.y, o1);
    }
    *(float2*)&out[node * 32 + j2 * 2] =
        make_float2(fmaxf(o0, 0.0f), fmaxf(o1, 0.0f));
}

// ---------------------------------------------------------------------------
// Launch — 5 kernels
// Inputs: x[N,4], edge_index[2,E], W1[4,64], b1[64], W2[64,32], b2[32],
//         Wf[32,32], bf[32]       Output: [N,32] float32
// ---------------------------------------------------------------------------
extern "C" void kernel_launch(void* const* d_in, const int* in_sizes, int n_in,
                              void* d_out, int out_size) {
    const float* x  = (const float*)d_in[0];
    const int*   ei = (const int*)d_in[1];
    const float* W1 = (const float*)d_in[2];
    const float* b1 = (const float*)d_in[3];
    const float* W2 = (const float*)d_in[4];
    const float* b2 = (const float*)d_in[5];
    const float* Wf = (const float*)d_in[6];
    const float* bf = (const float*)d_in[7];
    float* out = (float*)d_out;

    int n = in_sizes[0] / 4;
    int E = in_sizes[1] / 2;
    const int* src = ei;
    const int* dst = ei + E;

    const int T = 256;
    int nb = (n + SCAN_CHUNK - 1) / SCAN_CHUNK;

    k_deg<<<(E + T - 1) / T, T>>>(dst, E);
    k_scan<<<nb, SCAN_CHUNK>>>((const float4*)x, n);
    k_fill<<<(E + T - 1) / T, T>>>(src, dst, E);
    k_layer1<<<(n + 127) / 128, 128>>>(W1, b1, W2, n);
    k_final<<<(n + 15) / 16, T>>>(b2, Wf, bf, out, n);
}

// round 11
// speedup vs baseline: 1.0252x; 1.0252x over previous
#include <cuda_runtime.h>
#include <cuda_fp16.h>
#include <cuda_bf16.h>
#include <cstdint>

#define NMAX 100000
#define EMAX 1600000
#define SCAN_CHUNK 1024

// ---------------------------------------------------------------------------
// Scratch (device globals — zero-init at load; each consumer restores zeros
// so the invariant holds across CUDA-graph replays).
// ---------------------------------------------------------------------------
__device__ int    g_deg[NMAX];
__device__ int    g_off[NMAX];        // CSR range begin (by dst)
__device__ int    g_end[NMAX];        // CSR range end
__device__ int    g_rank[EMAX];       // edge rank within its dst bucket
__device__ int    g_csrc[EMAX];       // CSR column = src node BYTE offset (s*64)
__device__ int    g_base;             // global edge-slot counter
__device__ float  g_dinv[NMAX];
__device__ float  g_xs[NMAX * 4];     // x * dinv (pre-scaled layer-1 sources)
__device__ float  g_a1[NMAX * 4];     // layer-1 aggregate (REDs from k_fill)
__device__ __half g_h2h[NMAX * 32];   // (relu(v@W1+b1) @ W2) * dinv, fp16

// ---------------------------------------------------------------------------
// PTX helpers
// ---------------------------------------------------------------------------
__device__ __forceinline__ void red_add_v4(float* p, float4 v) {
    asm volatile(
        "{\n\t"
        ".reg .u64 q;\n\t"
        "cvta.to.global.u64 q, %0;\n\t"
        "red.global.add.v4.f32 [q], {%1, %2, %3, %4};\n\t"
        "}"
        :: "l"(p), "f"(v.x), "f"(v.y), "f"(v.z), "f"(v.w)
        : "memory");
}

__device__ __forceinline__ uint32_t h2u(__half2 h) {
    uint32_t u;
    memcpy(&u, &h, 4);
    return u;
}

// m16n8k16 fp16 MMA, fp32 accumulate (D = A@B + D)
__device__ __forceinline__ void hmma16816(float& c0, float& c1,
                                          float& c2, float& c3,
                                          uint32_t a0, uint32_t a1,
                                          uint32_t a2, uint32_t a3,
                                          uint32_t b0, uint32_t b1) {
    asm volatile(
        "mma.sync.aligned.m16n8k16.row.col.f32.f16.f16.f32 "
        "{%0,%1,%2,%3}, {%4,%5,%6,%7}, {%8,%9}, {%0,%1,%2,%3};"
        : "+f"(c0), "+f"(c1), "+f"(c2), "+f"(c3)
        : "r"(a0), "r"(a1), "r"(a2), "r"(a3), "r"(b0), "r"(b1));
}

// ---------------------------------------------------------------------------
// K1: degree over dst; rank[e] = arrival index within bucket; resets g_base
// ---------------------------------------------------------------------------
__global__ void k_deg(const int* __restrict__ dst, int E) {
    int e = blockIdx.x * blockDim.x + threadIdx.x;
    if (e == 0) g_base = 0;
    if (e < E) g_rank[e] = atomicAdd(&g_deg[dst[e]], 1);
}

// ---------------------------------------------------------------------------
// K2: single-pass chunked scan, atomic base per 1024-chunk (bucket ranges
//     disjoint, not globally sorted — g_end stores explicit ends). Also
//     computes dinv, pre-scales x, and ZEROES g_deg.
// ---------------------------------------------------------------------------
__global__ void __launch_bounds__(SCAN_CHUNK) k_scan(const float4* __restrict__ x4, int n) {
    __shared__ int swarp[32];
    __shared__ int sbase;
    int t = threadIdx.x;
    int lane = t & 31, wid = t >> 5;
    int i = blockIdx.x * SCAN_CHUNK + t;
    int v = (i < n) ? g_deg[i] : 0;

    int inc = v;
#pragma unroll
    for (int o = 1; o < 32; o <<= 1) {
        int y = __shfl_up_sync(0xffffffff, inc, o);
        if (lane >= o) inc += y;
    }
    if (lane == 31) swarp[wid] = inc;
    __syncthreads();
    if (t < 32) {
        int wv = swarp[t];
        int winc = wv;
#pragma unroll
        for (int o = 1; o < 32; o <<= 1) {
            int y = __shfl_up_sync(0xffffffff, winc, o);
            if (t >= o) winc += y;
        }
        swarp[t] = winc - wv;                          // exclusive warp base
        if (t == 31) sbase = atomicAdd(&g_base, winc); // winc = block total
    }
    __syncthreads();

    if (i < n) {
        int beg = sbase + swarp[wid] + (inc - v);
        g_off[i] = beg;
        g_end[i] = beg + v;
        float di = rsqrtf((float)(v + 1));             // +1 self-loop
        g_dinv[i] = di;
        float4 xv = x4[i];
        xv.x *= di; xv.y *= di; xv.z *= di; xv.w *= di;
        *(float4*)&g_xs[i * 4] = xv;
        g_deg[i] = 0;                                  // restore scratch
    }
}

// ---------------------------------------------------------------------------
// K3: bucket-fill CSR (atomic-free via precomputed rank) + layer-1 scatter:
//     csrc[off[d]+rank[e]] = src[e]*64 (byte offset);  a1[dst] += xs[src]
// ---------------------------------------------------------------------------
__global__ void k_fill(const int* __restrict__ src,
                       const int* __restrict__ dst, int E) {
    int e = blockIdx.x * blockDim.x + threadIdx.x;
    if (e >= E) return;
    int s = src[e], d = dst[e];
    g_csrc[g_off[d] + g_rank[e]] = s << 6;   // byte offset into g_h2h row
    red_add_v4(&g_a1[d * 4], *(const float4*)&g_xs[s * 4]);
}

// ---------------------------------------------------------------------------
// K4: layer-1 transform on TENSOR CORES (mma.sync m16n8k16 fp16->fp32).
//     Block = 128 thr = 4 warps; warp handles 16 nodes; block covers 64.
//     Per warp: h1[16,64] computed element-exact into A fragments (each lane
//     computes its own 8 elems/k-step — no duplication), W2 held in registers
//     as 16 B-fragments, 16 HMMA -> D[16,32] fp32, scale by dinv, store fp16.
//     Zeroes g_a1 after consuming it.
// ---------------------------------------------------------------------------
__global__ void __launch_bounds__(128) k_layer1(
        const float* __restrict__ W1,   // [4,64]
        const float* __restrict__ b1,   // [64]
        const float* __restrict__ W2,   // [64,32]
        int n) {
    __shared__ float4 sW1t[64];       // column f of W1
    __shared__ float  sb1[64];
    __shared__ __half sW2h[64 * 32];  // W2 in fp16, row-major [k][n]
    __shared__ float4 sv[64];         // v per node (block's 64 nodes)
    __shared__ float  sdi[64];

    int t = threadIdx.x;
    int w = t >> 5, lane = t & 31;
    int nb = blockIdx.x * 64;

    if (t < 64) {
        sW1t[t] = make_float4(W1[t], W1[64 + t], W1[128 + t], W1[192 + t]);
        sb1[t] = b1[t];
    }
    for (int i = t; i < 2048; i += 128) sW2h[i] = __float2half_rn(W2[i]);

    if (t < 64) {
        int node = nb + t;
        if (node < n) {
            float di = g_dinv[node];
            float4 a  = *(const float4*)&g_a1[node * 4];
            float4 xv = *(const float4*)&g_xs[node * 4];
            *(float4*)&g_a1[node * 4] = make_float4(0.f, 0.f, 0.f, 0.f);
            sv[t] = make_float4((a.x + xv.x) * di, (a.y + xv.y) * di,
                                (a.z + xv.z) * di, (a.w + xv.w) * di);
            sdi[t] = di;
        } else {
            sv[t] = make_float4(0.f, 0.f, 0.f, 0.f);
            sdi[t] = 0.f;
        }
    }
    __syncthreads();

    int gid = lane >> 2;      // 0..7  (row group / n index)
    int tid4 = lane & 3;      // 0..3  (col pair / k pair index)

    // ---- B fragments: W2 fp16, col-major frag map.
    // b0={B[k0][nn],B[k0+1][nn]}, b1={B[k0+8][nn],B[k0+9][nn]},
    // k0 = kk*16 + tid4*2, nn = nt*8 + gid.
    uint32_t bfr[4][4][2];
#pragma unroll
    for (int kk = 0; kk < 4; kk++) {
#pragma unroll
        for (int nt = 0; nt < 4; nt++) {
            int k0 = kk * 16 + tid4 * 2;
            int nn = nt * 8 + gid;
            bfr[kk][nt][0] = h2u(__halves2half2(sW2h[k0 * 32 + nn],
                                                sW2h[(k0 + 1) * 32 + nn]));
            bfr[kk][nt][1] = h2u(__halves2half2(sW2h[(k0 + 8) * 32 + nn],
                                                sW2h[(k0 + 9) * 32 + nn]));
        }
    }

    // ---- this lane's two node rows within the warp tile
    int r0 = w * 16 + gid;        // local row gid
    int r1 = r0 + 8;              // local row gid+8
    float4 v0 = sv[r0], v1 = sv[r1];
    float di0 = sdi[r0], di1 = sdi[r1];

    float c[4][4];
#pragma unroll
    for (int nt = 0; nt < 4; nt++)
#pragma unroll
        for (int k = 0; k < 4; k++) c[nt][k] = 0.0f;

#pragma unroll
    for (int kk = 0; kk < 4; kk++) {
        // A fragment: h1 at rows {gid, gid+8}, cols {c0,c0+1,c0+8,c0+9}+16kk
        int cc = kk * 16 + tid4 * 2;
        float4 wa = sW1t[cc],     wb = sW1t[cc + 1];
        float4 wc = sW1t[cc + 8], wd = sW1t[cc + 9];
        float ba = sb1[cc], bb = sb1[cc + 1];
        float bc = sb1[cc + 8], bd = sb1[cc + 9];

        float h00 = fmaxf(fmaf(v0.x, wa.x, fmaf(v0.y, wa.y, fmaf(v0.z, wa.z, fmaf(v0.w, wa.w, ba)))), 0.f);
        float h01 = fmaxf(fmaf(v0.x, wb.x, fmaf(v0.y, wb.y, fmaf(v0.z, wb.z, fmaf(v0.w, wb.w, bb)))), 0.f);
        float h02 = fmaxf(fmaf(v0.x, wc.x, fmaf(v0.y, wc.y, fmaf(v0.z, wc.z, fmaf(v0.w, wc.w, bc)))), 0.f);
        float h03 = fmaxf(fmaf(v0.x, wd.x, fmaf(v0.y, wd.y, fmaf(v0.z, wd.z, fmaf(v0.w, wd.w, bd)))), 0.f);
        float h10 = fmaxf(fmaf(v1.x, wa.x, fmaf(v1.y, wa.y, fmaf(v1.z, wa.z, fmaf(v1.w, wa.w, ba)))), 0.f);
        float h11 = fmaxf(fmaf(v1.x, wb.x, fmaf(v1.y, wb.y, fmaf(v1.z, wb.z, fmaf(v1.w, wb.w, bb)))), 0.f);
        float h12 = fmaxf(fmaf(v1.x, wc.x, fmaf(v1.y, wc.y, fmaf(v1.z, wc.z, fmaf(v1.w, wc.w, bc)))), 0.f);
        float h13 = fmaxf(fmaf(v1.x, wd.x, fmaf(v1.y, wd.y, fmaf(v1.z, wd.z, fmaf(v1.w, wd.w, bd)))), 0.f);

        uint32_t a0 = h2u(__floats2half2_rn(h00, h01));  // row gid,  cols c0,c0+1
        uint32_t a1 = h2u(__floats2half2_rn(h10, h11));  // row gid+8
        uint32_t a2 = h2u(__floats2half2_rn(h02, h03));  // row gid,  cols +8,+9
        uint32_t a3 = h2u(__floats2half2_rn(h12, h13));  // row gid+8

#pragma unroll
        for (int nt = 0; nt < 4; nt++)
            hmma16816(c[nt][0], c[nt][1], c[nt][2], c[nt][3],
                      a0, a1, a2, a3, bfr[kk][nt][0], bfr[kk][nt][1]);
    }

    // ---- epilogue: scale by dinv, fp16, store (guard tail nodes)
    int node0 = nb + r0;
    int node1 = nb + r1;
#pragma unroll
    for (int nt = 0; nt < 4; nt++) {
        int colb = nt * 8 + tid4 * 2;
        if (node0 < n) {
            __half2 lo = __floats2half2_rn(c[nt][0] * di0, c[nt][1] * di0);
            *(__half2*)&g_h2h[node0 * 32 + colb] = lo;
        }
        if (node1 < n) {
            __half2 hi = __floats2half2_rn(c[nt][2] * di1, c[nt][3] * di1);
            *(__half2*)&g_h2h[node1 * 32 + colb] = hi;
        }
    }
}

// ---------------------------------------------------------------------------
// K5: fused layer 2 + final linear. TWO nodes per warp:
//     lane = (half = lane>>4, j2 = lane&15) -> feature pair (2*j2, 2*j2+1)
//     Gather: one __half2 per lane per edge; a warp-instruction covers 2 edges.
//     h2  = relu(dinv*(sum_s h2h[s] + h2h[node]) + b2)
//     out = relu(h2 @ Wf + bf)
// ---------------------------------------------------------------------------
__global__ void __launch_bounds__(256) k_final(
        const float* __restrict__ b2,   // [32]
        const float* __restrict__ Wf,   // [32,32]
        const float* __restrict__ bf,   // [32]
        float* __restrict__ out, int n) {
    __shared__ float sWf[32 * 32];
    __shared__ float sb2[32];
    __shared__ float sbf[32];
    __shared__ float sh[16][32];        // 16 nodes per 256-thread block
    int t = threadIdx.x;
    for (int i = t; i < 1024; i += 256) sWf[i] = Wf[i];
    if (t < 32) { sb2[t] = b2[t]; sbf[t] = bf[t]; }
    __syncthreads();

    int w = t >> 5;
    int lane = t & 31;
    int half = lane >> 4;               // which node of the warp's pair
    int j2 = lane & 15;                 // feature pair index
    int slot = w * 2 + half;
    int node = blockIdx.x * 16 + slot;
    bool active = (node < n);

    const char* h2base = (const char*)g_h2h;
    int foff = j2 << 2;                 // byte offset of feature pair

    float ax = 0.0f, ay = 0.0f;
    float di = 0.0f;
    float2 selff = make_float2(0.f, 0.f);
    if (active) {
        int beg = g_off[node], end = g_end[node];
        int i = beg;
        for (; i + 4 <= end; i += 4) {
            int o0 = g_csrc[i + 0], o1 = g_csrc[i + 1];
            int o2 = g_csrc[i + 2], o3 = g_csrc[i + 3];
            __half2 m0 = *(const __half2*)(h2base + o0 + foff);
            __half2 m1 = *(const __half2*)(h2base + o1 + foff);
            __half2 m2 = *(const __half2*)(h2base + o2 + foff);
            __half2 m3 = *(const __half2*)(h2base + o3 + foff);
            float2 f0 = __half22float2(m0), f1 = __half22float2(m1);
            float2 f2 = __half22float2(m2), f3 = __half22float2(m3);
            ax += (f0.x + f1.x) + (f2.x + f3.x);
            ay += (f0.y + f1.y) + (f2.y + f3.y);
        }
        for (; i < end; i++) {
            __half2 m = *(const __half2*)(h2base + g_csrc[i] + foff);
            float2 f = __half22float2(m);
            ax += f.x; ay += f.y;
        }
        di = g_dinv[node];
        selff = __half22float2(*(const __half2*)(h2base + (node << 6) + foff));
    }

    float2 bb2 = *(const float2*)&sb2[j2 * 2];
    float h0 = fmaxf(fmaf(di, ax + selff.x, bb2.x), 0.0f);
    float h1 = fmaxf(fmaf(di, ay + selff.y, bb2.y), 0.0f);
    sh[slot][j2 * 2]     = h0;
    sh[slot][j2 * 2 + 1] = h1;
    __syncwarp();
    if (!active) return;

    float2 bbf = *(const float2*)&sbf[j2 * 2];
    float o0 = bbf.x, o1 = bbf.y;
#pragma unroll
    for (int k = 0; k < 32; k++) {
        float hk = sh[slot][k];
        float2 wv = *(const float2*)&sWf[k * 32 + j2 * 2];
        o0 = fmaf(hk, wv.x, o0);
        o1 = fmaf(hk, wv.y, o1);
    }
    *(float2*)&out[node * 32 + j2 * 2] =
        make_float2(fmaxf(o0, 0.0f), fmaxf(o1, 0.0f));
}

// ---------------------------------------------------------------------------
// Launch — 5 kernels
// Inputs: x[N,4], edge_index[2,E], W1[4,64], b1[64], W2[64,32], b2[32],
//         Wf[32,32], bf[32]       Output: [N,32] float32
// ---------------------------------------------------------------------------
extern "C" void kernel_launch(void* const* d_in, const int* in_sizes, int n_in,
                              void* d_out, int out_size) {
    const float* x  = (const float*)d_in[0];
    const int*   ei = (const int*)d_in[1];
    const float* W1 = (const float*)d_in[2];
    const float* b1 = (const float*)d_in[3];
    const float* W2 = (const float*)d_in[4];
    const float* b2 = (const float*)d_in[5];
    const float* Wf = (const float*)d_in[6];
    const float* bf = (const float*)d_in[7];
    float* out = (float*)d_out;

    int n = in_sizes[0] / 4;
    int E = in_sizes[1] / 2;
    const int* src = ei;
    const int* dst = ei + E;

    const int T = 256;
    int nb = (n + SCAN_CHUNK - 1) / SCAN_CHUNK;

    k_deg<<<(E + T - 1) / T, T>>>(dst, E);
    k_scan<<<nb, SCAN_CHUNK>>>((const float4*)x, n);
    k_fill<<<(E + T - 1) / T, T>>>(src, dst, E);
    k_layer1<<<(n + 63) / 64, 128>>>(W1, b1, W2, n);
    k_final<<<(n + 15) / 16, T>>>(b2, Wf, bf, out, n);
}